// round 15
// baseline (speedup 1.0000x reference)
#include <cuda_runtime.h>
#include <cuda_bf16.h>
#include <cstdint>

// ---------------------------------------------------------------------------
// GCN_21260088115434: 3-layer GCN + dot-product link decode.
//   dinv = rsqrt(1 + indeg)
//   layer: g = dinv ⊙ (h @ W)   (persistent pipelined mma.sync bf16-split GEMM)
//          h' = act(dinv ⊙ (g[v] + Σ_{(s→v)} g[s]) + b)   (CSR segment reduce)
//   out[p] = dot(z[a_p], z[b_p])
// R8 kernels + full-PDL prologue: W-image conversion (prep_w) overlaps the
// CSR edge fill; every dependent kernel early-launches and orders itself via
// griddepcontrol.wait. Edge indices are int32. tcgen05 unavailable (plain
// sm_103 target); griddepcontrol is baseline sm_90+.
// ---------------------------------------------------------------------------

#define MAX_N 100000
#define MAX_E 1600000
#define D_HID 128

__device__ float g_dinv[MAX_N];
__device__ float g_bufG[(size_t)MAX_N * D_HID];
__device__ float g_bufH[(size_t)MAX_N * D_HID];
__device__ __align__(16) __nv_bfloat16 g_hHi[(size_t)MAX_N * D_HID];
__device__ __align__(16) __nv_bfloat16 g_hLo[(size_t)MAX_N * D_HID];
__device__ int   g_cnt[MAX_N];
__device__ int   g_cur[MAX_N];
__device__ int   g_rowptr[MAX_N + 1];
__device__ int   g_csr[MAX_E];
// transposed bf16 weight images: Wt[n][k] (n-major), hi/lo split
__device__ __align__(16) __nv_bfloat16 g_W1hi[128 * 128];
__device__ __align__(16) __nv_bfloat16 g_W1lo[128 * 128];
__device__ __align__(16) __nv_bfloat16 g_W2hi[128 * 128];
__device__ __align__(16) __nv_bfloat16 g_W2lo[128 * 128];
__device__ __align__(16) __nv_bfloat16 g_W3hi[64 * 128];
__device__ __align__(16) __nv_bfloat16 g_W3lo[64 * 128];

// ---------------------------------------------------------------------------
__device__ __forceinline__ uint32_t smem_u32(const void* p) {
    uint32_t a;
    asm("{ .reg .u64 t; cvta.to.shared.u64 t, %1; cvt.u32.u64 %0, t; }"
        : "=r"(a) : "l"(p));
    return a;
}

#define GDC_WAIT() asm volatile("griddepcontrol.wait;" ::: "memory")

#define LDSM4(r0, r1, r2, r3, addr) \
    asm volatile("ldmatrix.sync.aligned.m8n8.x4.shared.b16 {%0,%1,%2,%3}, [%4];" \
                 : "=r"(r0), "=r"(r1), "=r"(r2), "=r"(r3) : "r"(addr))

#define MMA_BF16(c, a, b) \
    asm volatile("mma.sync.aligned.m16n8k16.row.col.f32.bf16.bf16.f32 " \
                 "{%0,%1,%2,%3}, {%4,%5,%6,%7}, {%8,%9}, {%0,%1,%2,%3};" \
                 : "+f"((c)[0]), "+f"((c)[1]), "+f"((c)[2]), "+f"((c)[3]) \
                 : "r"((a)[0]), "r"((a)[1]), "r"((a)[2]), "r"((a)[3]), \
                   "r"((b)[0]), "r"((b)[1]))

__device__ __forceinline__ void split_bf(float x, __nv_bfloat16& h, __nv_bfloat16& l) {
    h = __float2bfloat16(x);
    l = __float2bfloat16(x - __bfloat162float(h));
}
__device__ __forceinline__ uint32_t pack_bf2(__nv_bfloat16 a, __nv_bfloat16 b) {
    __nv_bfloat162 t;
    t.x = a; t.y = b;
    return *(uint32_t*)&t;
}

// ---------------------------------------------------------------------------
// prologue kernels
// ---------------------------------------------------------------------------
__global__ void prep_zero_kernel(int* cnt, int* cur, int n) {
    int i = blockIdx.x * blockDim.x + threadIdx.x;
    if (i < n) { cnt[i] = 0; cur[i] = 0; }
}

__device__ __forceinline__ void conv_w(const float* W, __nv_bfloat16* hiT,
                                       __nv_bfloat16* loT, int BN, int t) {
    int k = t / BN;
    int n = t % BN;
    __nv_bfloat16 h, l;
    split_bf(W[k * BN + n], h, l);
    hiT[n * 128 + k] = h;
    loT[n * 128 + k] = l;
}

// Runs concurrent with the CSR fill (PDL, no top wait). Reads only harness
// inputs; writes only its own images. END wait keeps the dependency chain
// transitive (fill completes before this grid retires).
__global__ void prep_w_kernel(const float* W1, const float* W2, const float* W3) {
    int i = blockIdx.x * blockDim.x + threadIdx.x;
    if (i < 16384)      conv_w(W1, g_W1hi, g_W1lo, 128, i);
    else if (i < 32768) conv_w(W2, g_W2hi, g_W2lo, 128, i - 16384);
    else if (i < 40960) conv_w(W3, g_W3hi, g_W3lo, 64,  i - 32768);
    GDC_WAIT();
}

__global__ void count_kernel(const int* __restrict__ dst, int* cnt, int e) {
    GDC_WAIT();
    int i = blockIdx.x * blockDim.x + threadIdx.x;
    if (i < e) atomicAdd(&cnt[dst[i]], 1);
}

// single-block exclusive scan of cnt -> rowptr, plus dinv = rsqrt(1+cnt)
__global__ void scan_dinv_kernel(const int* __restrict__ cnt,
                                 int* __restrict__ rowptr,
                                 float* __restrict__ dinv, int n) {
    GDC_WAIT();
    __shared__ int sums[1024];
    int tid = threadIdx.x;
    int chunk = (n + 1023) >> 10;
    int beg = tid * chunk;
    int end = min(beg + chunk, n);
    int s = 0;
    for (int i = beg; i < end; i++) s += cnt[i];
    sums[tid] = s;
    __syncthreads();
    int own = s;
    for (int d = 1; d < 1024; d <<= 1) {
        int v = (tid >= d) ? sums[tid - d] : 0;
        __syncthreads();
        sums[tid] += v;
        __syncthreads();
    }
    int off = sums[tid] - own;
    for (int i = beg; i < end; i++) {
        int c = cnt[i];
        rowptr[i] = off;
        dinv[i] = rsqrtf(1.0f + (float)c);
        off += c;
    }
    if (tid == 1023) rowptr[n] = off;
}

__global__ void fill_kernel(const int* __restrict__ src, const int* __restrict__ dst,
                            const int* __restrict__ rowptr, int* cur,
                            int* __restrict__ csr, int e) {
    GDC_WAIT();
    int i = blockIdx.x * blockDim.x + threadIdx.x;
    if (i < e) {
        int d = dst[i];
        int pos = rowptr[d] + atomicAdd(&cur[d], 1);
        csr[pos] = src[i];
    }
}

// ---------------------------------------------------------------------------
// Persistent, pipelined mma.sync bf16-split GEMM:
//   outG = dinv[row] * (A[N,128] @ W[128,BN])
// Grid=148 x 512 threads (16 warps, 4m x 4n). W in SMEM once. A double-
// buffered in SMEM; next tile prefetched into registers during MMA.
// PDL: !PRESPLIT (gemm1) waits at the very top (predecessor prep_w carries
// the whole prologue chain); PRESPLIT gemms wait after the W smem load.
// ---------------------------------------------------------------------------
template <int BN, bool PRESPLIT>
__global__ __launch_bounds__(512)
void gemm_mma_kernel(const float* __restrict__ A,
                     const uint4* __restrict__ aHi,
                     const uint4* __restrict__ aLo,
                     const __nv_bfloat16* __restrict__ wtHi,
                     const __nv_bfloat16* __restrict__ wtLo,
                     const float* __restrict__ dinv,
                     float* __restrict__ outG, int nrows, int ntiles) {
    constexpr int SROW = 272;
    constexpr int W_HI = 0;
    constexpr int W_LO = BN * SROW;
    constexpr int AB0 = 2 * BN * SROW;          // A buffer 0
    constexpr int ALO = 128 * SROW;             // lo offset within an A buffer
    constexpr int ABSZ = 2 * 128 * SROW;        // bytes per A buffer (hi+lo)
    constexpr int NTW = BN / 32;                // n8-tiles per warp
    constexpr int NP = NTW / 2;                 // 16-col groups per warp

    extern __shared__ char sm[];
    const uint32_t smb = smem_u32(sm);
    const int tid = threadIdx.x;
    const int wid = tid >> 5, lane = tid & 31;
    const int mrow = (wid & 3) * 32;
    const int ncol = (wid >> 2) * (BN / 4);
    const int r = lane & 15;
    const int koff = (lane >> 4) * 16;
    const int g = lane >> 2, tq = lane & 3;
    const int m = tid >> 2;                     // A-copy row 0..127
    const int q = tid & 3;                      // A-copy chunk group

    if (!PRESPLIT) GDC_WAIT();  // W images come from immediate predecessor

    // ---- W images -> SMEM once ----
    for (int c = tid; c < BN * 16; c += 512) {
        int n = c >> 4, kc = c & 15;
        *(uint4*)(sm + W_HI + n * SROW + kc * 16) = *(const uint4*)(wtHi + n * 128 + kc * 8);
        *(uint4*)(sm + W_LO + n * SROW + kc * 16) = *(const uint4*)(wtLo + n * 128 + kc * 8);
    }

    if (PRESPLIT) GDC_WAIT();   // A images come from the immediate predecessor

    // prefetch registers
    uint4 rh[4], rl[4];     // PRESPLIT path
    float4 rf[8];           // fp32 path

    auto prefetch = [&](int tile) {
        bool ok = (tile < ntiles) && (tile * 128 + m < nrows);
        int grow = tile * 128 + m;
        if (PRESPLIT) {
#pragma unroll
            for (int j = 0; j < 4; j++) {
                rh[j] = ok ? aHi[(size_t)grow * 16 + q * 4 + j]
                           : make_uint4(0, 0, 0, 0);
                rl[j] = ok ? aLo[(size_t)grow * 16 + q * 4 + j]
                           : make_uint4(0, 0, 0, 0);
            }
        } else {
            const float4* Arow = (const float4*)(A + (size_t)grow * 128 + q * 32);
#pragma unroll
            for (int j = 0; j < 8; j++)
                rf[j] = ok ? Arow[j] : make_float4(0.f, 0.f, 0.f, 0.f);
        }
    };

    prefetch(blockIdx.x);
    int buf = 0;

    for (int tile = blockIdx.x; tile < ntiles; tile += gridDim.x) {
        const int row0 = tile * 128;
        const int abase = AB0 + buf * ABSZ;

        // ---- store prefetched A into SMEM ----
        if (PRESPLIT) {
            char* hRow = sm + abase + m * SROW + q * 64;
            char* lRow = hRow + ALO;
#pragma unroll
            for (int j = 0; j < 4; j++) {
                *(uint4*)(hRow + j * 16) = rh[j];
                *(uint4*)(lRow + j * 16) = rl[j];
            }
        } else {
            char* hRow = sm + abase + m * SROW + q * 64;
            char* lRow = hRow + ALO;
#pragma unroll
            for (int j = 0; j < 8; j++) {
                float4 v = rf[j];
                __nv_bfloat16 h0, h1, h2, h3, l0, l1, l2, l3;
                split_bf(v.x, h0, l0);
                split_bf(v.y, h1, l1);
                split_bf(v.z, h2, l2);
                split_bf(v.w, h3, l3);
                *(uint32_t*)(hRow + j * 8)     = pack_bf2(h0, h1);
                *(uint32_t*)(hRow + j * 8 + 4) = pack_bf2(h2, h3);
                *(uint32_t*)(lRow + j * 8)     = pack_bf2(l0, l1);
                *(uint32_t*)(lRow + j * 8 + 4) = pack_bf2(l2, l3);
            }
        }
        __syncthreads();

        // ---- prefetch next tile while MMAs run ----
        prefetch(tile + gridDim.x);

        float acc[2][NTW][4] = {};
#pragma unroll
        for (int ks = 0; ks < 8; ks++) {
            const int kb = ks * 32 + koff;
            uint32_t ahi[2][4], alo[2][4];
#pragma unroll
            for (int mt = 0; mt < 2; mt++) {
                uint32_t ad = smb + abase + (mrow + mt * 16 + r) * SROW + kb;
                LDSM4(ahi[mt][0], ahi[mt][1], ahi[mt][2], ahi[mt][3], ad);
                LDSM4(alo[mt][0], alo[mt][1], alo[mt][2], alo[mt][3], ad + ALO);
            }
#pragma unroll
            for (int np = 0; np < NP; np++) {
                uint32_t bd = smb + W_HI + (ncol + np * 16 + r) * SROW + kb;
                uint32_t h0, h1, h2, h3, q0, q1, q2, q3;
                LDSM4(h0, h1, h2, h3, bd);
                LDSM4(q0, q1, q2, q3, bd + W_LO);
                uint32_t bh0[2] = {h0, h2}, bh1[2] = {h1, h3};
                uint32_t bl0[2] = {q0, q2}, bl1[2] = {q1, q3};
#pragma unroll
                for (int mt = 0; mt < 2; mt++) {
                    MMA_BF16(acc[mt][2 * np],     ahi[mt], bh0);
                    MMA_BF16(acc[mt][2 * np],     ahi[mt], bl0);
                    MMA_BF16(acc[mt][2 * np],     alo[mt], bh0);
                    MMA_BF16(acc[mt][2 * np + 1], ahi[mt], bh1);
                    MMA_BF16(acc[mt][2 * np + 1], ahi[mt], bl1);
                    MMA_BF16(acc[mt][2 * np + 1], alo[mt], bh1);
                }
            }
        }

        // ---- epilogue: scale by dinv, store float2 pairs ----
#pragma unroll
        for (int mt = 0; mt < 2; mt++) {
            int r0g = row0 + mrow + mt * 16 + g;
            int r1g = r0g + 8;
            float dv0 = (r0g < nrows) ? dinv[r0g] : 0.f;
            float dv1 = (r1g < nrows) ? dinv[r1g] : 0.f;
#pragma unroll
            for (int nt = 0; nt < NTW; nt++) {
                int cc = ncol + nt * 8 + 2 * tq;
                if (r0g < nrows) {
                    float2 v = make_float2(acc[mt][nt][0] * dv0, acc[mt][nt][1] * dv0);
                    *(float2*)(outG + (size_t)r0g * BN + cc) = v;
                }
                if (r1g < nrows) {
                    float2 v = make_float2(acc[mt][nt][2] * dv1, acc[mt][nt][3] * dv1);
                    *(float2*)(outG + (size_t)r1g * BN + cc) = v;
                }
            }
        }
        buf ^= 1;
    }
}

// ---------------------------------------------------------------------------
// CSR aggregation + epilogue. OUTBF: emit bf16 hi/lo split pair (for next
// GEMM); else emit fp32. PDL: waits for predecessor (the GEMM) at the top.
// ---------------------------------------------------------------------------
template <int D, bool RELU, bool OUTBF>
__global__ void aggregate_kernel(const float* __restrict__ g,
                                 const int* __restrict__ rowptr,
                                 const int* __restrict__ csr,
                                 const float* __restrict__ dinv,
                                 const float* __restrict__ bias,
                                 float* __restrict__ out,
                                 uint2* __restrict__ outHi,
                                 uint2* __restrict__ outLo, int n) {
    GDC_WAIT();
    constexpr int TPN = D / 4;
    int t = blockIdx.x * blockDim.x + threadIdx.x;
    int v = t / TPN;
    int l = t % TPN;
    if (v >= n) return;
    const float4* g4 = (const float4*)g;

    float4 acc = g4[(size_t)v * TPN + l];   // self-loop
    int beg = rowptr[v], end = rowptr[v + 1];
    int j = beg;
    for (; j + 2 <= end; j += 2) {
        int s0 = csr[j], s1 = csr[j + 1];
        float4 m0 = g4[(size_t)s0 * TPN + l];
        float4 m1 = g4[(size_t)s1 * TPN + l];
        acc.x += m0.x + m1.x;
        acc.y += m0.y + m1.y;
        acc.z += m0.z + m1.z;
        acc.w += m0.w + m1.w;
    }
    if (j < end) {
        float4 m = g4[(size_t)csr[j] * TPN + l];
        acc.x += m.x; acc.y += m.y; acc.z += m.z; acc.w += m.w;
    }

    float dv = dinv[v];
    float4 b = ((const float4*)bias)[l];
    acc.x = acc.x * dv + b.x;
    acc.y = acc.y * dv + b.y;
    acc.z = acc.z * dv + b.z;
    acc.w = acc.w * dv + b.w;
    if (RELU) {
        acc.x = fmaxf(acc.x, 0.f);
        acc.y = fmaxf(acc.y, 0.f);
        acc.z = fmaxf(acc.z, 0.f);
        acc.w = fmaxf(acc.w, 0.f);
    }
    if (OUTBF) {
        __nv_bfloat16 h0, h1, h2, h3, l0, l1, l2, l3;
        split_bf(acc.x, h0, l0);
        split_bf(acc.y, h1, l1);
        split_bf(acc.z, h2, l2);
        split_bf(acc.w, h3, l3);
        uint2 hv = make_uint2(pack_bf2(h0, h1), pack_bf2(h2, h3));
        uint2 lv = make_uint2(pack_bf2(l0, l1), pack_bf2(l2, l3));
        outHi[(size_t)v * TPN + l] = hv;
        outLo[(size_t)v * TPN + l] = lv;
    } else {
        ((float4*)out)[(size_t)v * TPN + l] = acc;
    }
}

// ---------------------------------------------------------------------------
__global__ void decode_kernel(const float* __restrict__ z,
                              const int* __restrict__ ia,
                              const int* __restrict__ ib,
                              float* __restrict__ out, int npairs) {
    GDC_WAIT();
    int t = blockIdx.x * blockDim.x + threadIdx.x;
    int p = t >> 4;
    int l = t & 15;
    if (p >= npairs) return;
    int a = ia[p];
    int b = ib[p];
    float4 va = ((const float4*)z)[(size_t)a * 16 + l];
    float4 vb = ((const float4*)z)[(size_t)b * 16 + l];
    float s = va.x * vb.x + va.y * vb.y + va.z * vb.z + va.w * vb.w;
#pragma unroll
    for (int off = 8; off > 0; off >>= 1)
        s += __shfl_down_sync(0xffffffffu, s, off, 16);
    if (l == 0) out[p] = s;
}

// ---------------------------------------------------------------------------
// PDL launch helper
// ---------------------------------------------------------------------------
template <typename F, typename... Args>
static inline void pdl_launch(F kern, dim3 grid, dim3 block, size_t smem,
                              Args... args) {
    cudaLaunchConfig_t cfg = {};
    cfg.gridDim = grid;
    cfg.blockDim = block;
    cfg.dynamicSmemBytes = smem;
    cfg.stream = 0;
    cudaLaunchAttribute attr[1];
    attr[0].id = cudaLaunchAttributeProgrammaticStreamSerialization;
    attr[0].val.programmaticStreamSerializationAllowed = 1;
    cfg.attrs = attr;
    cfg.numAttrs = 1;
    cudaLaunchKernelEx(&cfg, kern, args...);
}

// ---------------------------------------------------------------------------
extern "C" void kernel_launch(void* const* d_in, const int* in_sizes, int n_in,
                              void* d_out, int out_size) {
    const float* x = (const float*)d_in[0];
    const int* ei = (const int*)d_in[1];        // int32
    const int* eli = (const int*)d_in[2];
    const float* W1 = (const float*)d_in[3];
    const float* b1 = (const float*)d_in[4];
    const float* W2 = (const float*)d_in[5];
    const float* b2 = (const float*)d_in[6];
    const float* W3 = (const float*)d_in[7];
    const float* b3 = (const float*)d_in[8];
    float* out = (float*)d_out;

    const int N = in_sizes[0] / 128;
    const int E = in_sizes[1] / 2;
    const int EL = in_sizes[2] / 2;

    const int* src = ei;
    const int* dst = ei + E;

    float* dinv;  cudaGetSymbolAddress((void**)&dinv, g_dinv);
    float* bufG;  cudaGetSymbolAddress((void**)&bufG, g_bufG);
    float* bufH;  cudaGetSymbolAddress((void**)&bufH, g_bufH);
    int* cnt;     cudaGetSymbolAddress((void**)&cnt, g_cnt);
    int* cur;     cudaGetSymbolAddress((void**)&cur, g_cur);
    int* rowptr;  cudaGetSymbolAddress((void**)&rowptr, g_rowptr);
    int* csr;     cudaGetSymbolAddress((void**)&csr, g_csr);
    uint4* hHi;   cudaGetSymbolAddress((void**)&hHi, g_hHi);
    uint4* hLo;   cudaGetSymbolAddress((void**)&hLo, g_hLo);
    __nv_bfloat16 *w1h, *w1l, *w2h, *w2l, *w3h, *w3l;
    cudaGetSymbolAddress((void**)&w1h, g_W1hi);
    cudaGetSymbolAddress((void**)&w1l, g_W1lo);
    cudaGetSymbolAddress((void**)&w2h, g_W2hi);
    cudaGetSymbolAddress((void**)&w2l, g_W2lo);
    cudaGetSymbolAddress((void**)&w3h, g_W3hi);
    cudaGetSymbolAddress((void**)&w3l, g_W3lo);

    constexpr int SROW = 272;
    constexpr int SMEM128 = 2 * 128 * SROW + 2 * (2 * 128 * SROW);  // 208896
    constexpr int SMEM64  = 2 * 64 * SROW + 2 * (2 * 128 * SROW);   // 174080
    cudaFuncSetAttribute(gemm_mma_kernel<128, false>,
                         cudaFuncAttributeMaxDynamicSharedMemorySize, SMEM128);
    cudaFuncSetAttribute(gemm_mma_kernel<128, true>,
                         cudaFuncAttributeMaxDynamicSharedMemorySize, SMEM128);
    cudaFuncSetAttribute(gemm_mma_kernel<64, true>,
                         cudaFuncAttributeMaxDynamicSharedMemorySize, SMEM64);

    const int TB = 256;
    const int ntiles = (N + 127) / 128;
    const int persGrid = 148;
    const int agg128 = (N * 32 + TB - 1) / TB;
    const int agg64  = (N * 16 + TB - 1) / TB;

    // prologue: zero -> count -> scan -> fill, with prep_w overlapping fill
    prep_zero_kernel<<<(N + TB - 1) / TB, TB>>>(cnt, cur, N);
    pdl_launch(count_kernel, dim3((E + TB - 1) / TB), dim3(TB), (size_t)0,
               dst, cnt, E);
    pdl_launch(scan_dinv_kernel, dim3(1), dim3(1024), (size_t)0,
               (const int*)cnt, rowptr, dinv, N);
    pdl_launch(fill_kernel, dim3((E + TB - 1) / TB), dim3(TB), (size_t)0,
               src, dst, (const int*)rowptr, cur, csr, E);
    // prep_w: NO top wait (independent of CSR chain) -> overlaps fill;
    // END wait keeps the chain transitive.
    pdl_launch(prep_w_kernel, dim3((40960 + TB - 1) / TB), dim3(TB), (size_t)0,
               W1, W2, W3);

    // layer-1 GEMM (fp32 A, in-kernel split); top wait covers whole prologue
    pdl_launch(gemm_mma_kernel<128, false>, dim3(persGrid), dim3(512), (size_t)SMEM128,
               x, (const uint4*)nullptr, (const uint4*)nullptr,
               (const __nv_bfloat16*)w1h, (const __nv_bfloat16*)w1l,
               (const float*)dinv, bufG, N, ntiles);

    // layer 1 aggregate -> bf16 hi/lo activation
    pdl_launch(aggregate_kernel<128, true, true>, dim3(agg128), dim3(TB), (size_t)0,
               (const float*)bufG, (const int*)rowptr, (const int*)csr,
               (const float*)dinv, b1, (float*)nullptr, (uint2*)hHi, (uint2*)hLo, N);

    // layer 2 (pre-split A)
    pdl_launch(gemm_mma_kernel<128, true>, dim3(persGrid), dim3(512), (size_t)SMEM128,
               (const float*)nullptr, (const uint4*)hHi, (const uint4*)hLo,
               (const __nv_bfloat16*)w2h, (const __nv_bfloat16*)w2l,
               (const float*)dinv, bufG, N, ntiles);
    pdl_launch(aggregate_kernel<128, true, true>, dim3(agg128), dim3(TB), (size_t)0,
               (const float*)bufG, (const int*)rowptr, (const int*)csr,
               (const float*)dinv, b2, (float*)nullptr, (uint2*)hHi, (uint2*)hLo, N);

    // layer 3 (D=64, pre-split A, fp32 out, no relu)
    pdl_launch(gemm_mma_kernel<64, true>, dim3(persGrid), dim3(512), (size_t)SMEM64,
               (const float*)nullptr, (const uint4*)hHi, (const uint4*)hLo,
               (const __nv_bfloat16*)w3h, (const __nv_bfloat16*)w3l,
               (const float*)dinv, bufG, N, ntiles);
    pdl_launch(aggregate_kernel<64, false, false>, dim3(agg64), dim3(TB), (size_t)0,
               (const float*)bufG, (const int*)rowptr, (const int*)csr,
               (const float*)dinv, b3, bufH, (uint2*)nullptr, (uint2*)nullptr, N);

    // decode
    pdl_launch(decode_kernel, dim3((int)(((long long)EL * 16 + TB - 1) / TB)),
               dim3(TB), (size_t)0,
               (const float*)bufH, (const int*)eli, (const int*)(eli + EL), out, EL);
}

// round 16
// speedup vs baseline: 1.0151x; 1.0151x over previous
#include <cuda_runtime.h>
#include <cuda_bf16.h>
#include <cstdint>

// ---------------------------------------------------------------------------
// GCN_21260088115434: 3-layer GCN + dot-product link decode.
//   dinv = rsqrt(1 + indeg)
//   layer: g = dinv ⊙ (h @ W)   (persistent pipelined mma.sync bf16-split GEMM)
//          h' = act(dinv ⊙ (g[v] + Σ_{(s→v)} g[s]) + b)   (CSR segment reduce)
//   out[p] = dot(z[a_p], z[b_p])
// R14 structure (best: 469.4us): prep->count->scan->fill, gemm1 PDL overlaps
// fill with END-wait only; PRESPLIT gemms wait after the W smem load; aggs &
// decode top-wait. This round adds PDL top-waits to count/scan/fill to hide
// their launch latencies. Edge indices are int32. tcgen05 unavailable (plain
// sm_103 target); griddepcontrol is baseline sm_90+.
// ---------------------------------------------------------------------------

#define MAX_N 100000
#define MAX_E 1600000
#define D_HID 128

__device__ float g_dinv[MAX_N];
__device__ float g_bufG[(size_t)MAX_N * D_HID];
__device__ float g_bufH[(size_t)MAX_N * D_HID];
__device__ __align__(16) __nv_bfloat16 g_hHi[(size_t)MAX_N * D_HID];
__device__ __align__(16) __nv_bfloat16 g_hLo[(size_t)MAX_N * D_HID];
__device__ int   g_cnt[MAX_N];
__device__ int   g_cur[MAX_N];
__device__ int   g_rowptr[MAX_N + 1];
__device__ int   g_csr[MAX_E];
// transposed bf16 weight images: Wt[n][k] (n-major), hi/lo split
__device__ __align__(16) __nv_bfloat16 g_W1hi[128 * 128];
__device__ __align__(16) __nv_bfloat16 g_W1lo[128 * 128];
__device__ __align__(16) __nv_bfloat16 g_W2hi[128 * 128];
__device__ __align__(16) __nv_bfloat16 g_W2lo[128 * 128];
__device__ __align__(16) __nv_bfloat16 g_W3hi[64 * 128];
__device__ __align__(16) __nv_bfloat16 g_W3lo[64 * 128];

// ---------------------------------------------------------------------------
__device__ __forceinline__ uint32_t smem_u32(const void* p) {
    uint32_t a;
    asm("{ .reg .u64 t; cvta.to.shared.u64 t, %1; cvt.u32.u64 %0, t; }"
        : "=r"(a) : "l"(p));
    return a;
}

#define GDC_WAIT() asm volatile("griddepcontrol.wait;" ::: "memory")

#define LDSM4(r0, r1, r2, r3, addr) \
    asm volatile("ldmatrix.sync.aligned.m8n8.x4.shared.b16 {%0,%1,%2,%3}, [%4];" \
                 : "=r"(r0), "=r"(r1), "=r"(r2), "=r"(r3) : "r"(addr))

#define MMA_BF16(c, a, b) \
    asm volatile("mma.sync.aligned.m16n8k16.row.col.f32.bf16.bf16.f32 " \
                 "{%0,%1,%2,%3}, {%4,%5,%6,%7}, {%8,%9}, {%0,%1,%2,%3};" \
                 : "+f"((c)[0]), "+f"((c)[1]), "+f"((c)[2]), "+f"((c)[3]) \
                 : "r"((a)[0]), "r"((a)[1]), "r"((a)[2]), "r"((a)[3]), \
                   "r"((b)[0]), "r"((b)[1]))

__device__ __forceinline__ void split_bf(float x, __nv_bfloat16& h, __nv_bfloat16& l) {
    h = __float2bfloat16(x);
    l = __float2bfloat16(x - __bfloat162float(h));
}
__device__ __forceinline__ uint32_t pack_bf2(__nv_bfloat16 a, __nv_bfloat16 b) {
    __nv_bfloat162 t;
    t.x = a; t.y = b;
    return *(uint32_t*)&t;
}

// ---------------------------------------------------------------------------
// prep: zero cnt/cur + build transposed hi/lo bf16 weight images
// ---------------------------------------------------------------------------
__device__ __forceinline__ void conv_w(const float* W, __nv_bfloat16* hiT,
                                       __nv_bfloat16* loT, int BN, int t) {
    int k = t / BN;
    int n = t % BN;
    __nv_bfloat16 h, l;
    split_bf(W[k * BN + n], h, l);
    hiT[n * 128 + k] = h;
    loT[n * 128 + k] = l;
}

__global__ void prep_kernel(int* cnt, int* cur, int n,
                            const float* W1, const float* W2, const float* W3) {
    int i = blockIdx.x * blockDim.x + threadIdx.x;
    if (i < n) { cnt[i] = 0; cur[i] = 0; }
    if (i < 16384)      conv_w(W1, g_W1hi, g_W1lo, 128, i);
    else if (i < 32768) conv_w(W2, g_W2hi, g_W2lo, 128, i - 16384);
    else if (i < 40960) conv_w(W3, g_W3hi, g_W3lo, 64,  i - 32768);
}

__global__ void count_kernel(const int* __restrict__ dst, int* cnt, int e) {
    GDC_WAIT();   // cnt zeroed by prep
    int i = blockIdx.x * blockDim.x + threadIdx.x;
    if (i < e) atomicAdd(&cnt[dst[i]], 1);
}

// single-block exclusive scan of cnt -> rowptr, plus dinv = rsqrt(1+cnt)
__global__ void scan_dinv_kernel(const int* __restrict__ cnt,
                                 int* __restrict__ rowptr,
                                 float* __restrict__ dinv, int n) {
    GDC_WAIT();   // counts complete
    __shared__ int sums[1024];
    int tid = threadIdx.x;
    int chunk = (n + 1023) >> 10;
    int beg = tid * chunk;
    int end = min(beg + chunk, n);
    int s = 0;
    for (int i = beg; i < end; i++) s += cnt[i];
    sums[tid] = s;
    __syncthreads();
    int own = s;
    for (int d = 1; d < 1024; d <<= 1) {
        int v = (tid >= d) ? sums[tid - d] : 0;
        __syncthreads();
        sums[tid] += v;
        __syncthreads();
    }
    int off = sums[tid] - own;
    for (int i = beg; i < end; i++) {
        int c = cnt[i];
        rowptr[i] = off;
        dinv[i] = rsqrtf(1.0f + (float)c);
        off += c;
    }
    if (tid == 1023) rowptr[n] = off;
}

__global__ void fill_kernel(const int* __restrict__ src, const int* __restrict__ dst,
                            const int* __restrict__ rowptr, int* cur,
                            int* __restrict__ csr, int e) {
    GDC_WAIT();   // rowptr ready
    int i = blockIdx.x * blockDim.x + threadIdx.x;
    if (i < e) {
        int d = dst[i];
        int pos = rowptr[d] + atomicAdd(&cur[d], 1);
        csr[pos] = src[i];
    }
}

// ---------------------------------------------------------------------------
// Persistent, pipelined mma.sync bf16-split GEMM:
//   outG = dinv[row] * (A[N,128] @ W[128,BN])
// Grid=148 x 512 threads (16 warps, 4m x 4n). W in SMEM once. A double-
// buffered in SMEM; next tile prefetched into registers during MMA.
// PDL: PRESPLIT gemms wait after the W-load (A comes from the immediate
// predecessor agg); the fp32 gemm1 reads nothing from its predecessor (fill;
// dinv comes from scan which completed before fill started) and waits only
// at the END (transitive ordering for the following agg).
// ---------------------------------------------------------------------------
template <int BN, bool PRESPLIT>
__global__ __launch_bounds__(512)
void gemm_mma_kernel(const float* __restrict__ A,
                     const uint4* __restrict__ aHi,
                     const uint4* __restrict__ aLo,
                     const __nv_bfloat16* __restrict__ wtHi,
                     const __nv_bfloat16* __restrict__ wtLo,
                     const float* __restrict__ dinv,
                     float* __restrict__ outG, int nrows, int ntiles) {
    constexpr int SROW = 272;
    constexpr int W_HI = 0;
    constexpr int W_LO = BN * SROW;
    constexpr int AB0 = 2 * BN * SROW;          // A buffer 0
    constexpr int ALO = 128 * SROW;             // lo offset within an A buffer
    constexpr int ABSZ = 2 * 128 * SROW;        // bytes per A buffer (hi+lo)
    constexpr int NTW = BN / 32;                // n8-tiles per warp
    constexpr int NP = NTW / 2;                 // 16-col groups per warp

    extern __shared__ char sm[];
    const uint32_t smb = smem_u32(sm);
    const int tid = threadIdx.x;
    const int wid = tid >> 5, lane = tid & 31;
    const int mrow = (wid & 3) * 32;
    const int ncol = (wid >> 2) * (BN / 4);
    const int r = lane & 15;
    const int koff = (lane >> 4) * 16;
    const int g = lane >> 2, tq = lane & 3;
    const int m = tid >> 2;                     // A-copy row 0..127
    const int q = tid & 3;                      // A-copy chunk group

    // ---- W images -> SMEM once (W from prep: safe before the PDL wait) ----
    for (int c = tid; c < BN * 16; c += 512) {
        int n = c >> 4, kc = c & 15;
        *(uint4*)(sm + W_HI + n * SROW + kc * 16) = *(const uint4*)(wtHi + n * 128 + kc * 8);
        *(uint4*)(sm + W_LO + n * SROW + kc * 16) = *(const uint4*)(wtLo + n * 128 + kc * 8);
    }

    if (PRESPLIT) GDC_WAIT();   // A images come from the immediate predecessor

    // prefetch registers
    uint4 rh[4], rl[4];     // PRESPLIT path
    float4 rf[8];           // fp32 path

    auto prefetch = [&](int tile) {
        bool ok = (tile < ntiles) && (tile * 128 + m < nrows);
        int grow = tile * 128 + m;
        if (PRESPLIT) {
#pragma unroll
            for (int j = 0; j < 4; j++) {
                rh[j] = ok ? aHi[(size_t)grow * 16 + q * 4 + j]
                           : make_uint4(0, 0, 0, 0);
                rl[j] = ok ? aLo[(size_t)grow * 16 + q * 4 + j]
                           : make_uint4(0, 0, 0, 0);
            }
        } else {
            const float4* Arow = (const float4*)(A + (size_t)grow * 128 + q * 32);
#pragma unroll
            for (int j = 0; j < 8; j++)
                rf[j] = ok ? Arow[j] : make_float4(0.f, 0.f, 0.f, 0.f);
        }
    };

    prefetch(blockIdx.x);
    int buf = 0;

    for (int tile = blockIdx.x; tile < ntiles; tile += gridDim.x) {
        const int row0 = tile * 128;
        const int abase = AB0 + buf * ABSZ;

        // ---- store prefetched A into SMEM ----
        if (PRESPLIT) {
            char* hRow = sm + abase + m * SROW + q * 64;
            char* lRow = hRow + ALO;
#pragma unroll
            for (int j = 0; j < 4; j++) {
                *(uint4*)(hRow + j * 16) = rh[j];
                *(uint4*)(lRow + j * 16) = rl[j];
            }
        } else {
            char* hRow = sm + abase + m * SROW + q * 64;
            char* lRow = hRow + ALO;
#pragma unroll
            for (int j = 0; j < 8; j++) {
                float4 v = rf[j];
                __nv_bfloat16 h0, h1, h2, h3, l0, l1, l2, l3;
                split_bf(v.x, h0, l0);
                split_bf(v.y, h1, l1);
                split_bf(v.z, h2, l2);
                split_bf(v.w, h3, l3);
                *(uint32_t*)(hRow + j * 8)     = pack_bf2(h0, h1);
                *(uint32_t*)(hRow + j * 8 + 4) = pack_bf2(h2, h3);
                *(uint32_t*)(lRow + j * 8)     = pack_bf2(l0, l1);
                *(uint32_t*)(lRow + j * 8 + 4) = pack_bf2(l2, l3);
            }
        }
        __syncthreads();

        // ---- prefetch next tile while MMAs run ----
        prefetch(tile + gridDim.x);

        float acc[2][NTW][4] = {};
#pragma unroll
        for (int ks = 0; ks < 8; ks++) {
            const int kb = ks * 32 + koff;
            uint32_t ahi[2][4], alo[2][4];
#pragma unroll
            for (int mt = 0; mt < 2; mt++) {
                uint32_t ad = smb + abase + (mrow + mt * 16 + r) * SROW + kb;
                LDSM4(ahi[mt][0], ahi[mt][1], ahi[mt][2], ahi[mt][3], ad);
                LDSM4(alo[mt][0], alo[mt][1], alo[mt][2], alo[mt][3], ad + ALO);
            }
#pragma unroll
            for (int np = 0; np < NP; np++) {
                uint32_t bd = smb + W_HI + (ncol + np * 16 + r) * SROW + kb;
                uint32_t h0, h1, h2, h3, q0, q1, q2, q3;
                LDSM4(h0, h1, h2, h3, bd);
                LDSM4(q0, q1, q2, q3, bd + W_LO);
                uint32_t bh0[2] = {h0, h2}, bh1[2] = {h1, h3};
                uint32_t bl0[2] = {q0, q2}, bl1[2] = {q1, q3};
#pragma unroll
                for (int mt = 0; mt < 2; mt++) {
                    MMA_BF16(acc[mt][2 * np],     ahi[mt], bh0);
                    MMA_BF16(acc[mt][2 * np],     ahi[mt], bl0);
                    MMA_BF16(acc[mt][2 * np],     alo[mt], bh0);
                    MMA_BF16(acc[mt][2 * np + 1], ahi[mt], bh1);
                    MMA_BF16(acc[mt][2 * np + 1], ahi[mt], bl1);
                    MMA_BF16(acc[mt][2 * np + 1], alo[mt], bh1);
                }
            }
        }

        // ---- epilogue: scale by dinv, store float2 pairs ----
#pragma unroll
        for (int mt = 0; mt < 2; mt++) {
            int r0g = row0 + mrow + mt * 16 + g;
            int r1g = r0g + 8;
            float dv0 = (r0g < nrows) ? dinv[r0g] : 0.f;
            float dv1 = (r1g < nrows) ? dinv[r1g] : 0.f;
#pragma unroll
            for (int nt = 0; nt < NTW; nt++) {
                int cc = ncol + nt * 8 + 2 * tq;
                if (r0g < nrows) {
                    float2 v = make_float2(acc[mt][nt][0] * dv0, acc[mt][nt][1] * dv0);
                    *(float2*)(outG + (size_t)r0g * BN + cc) = v;
                }
                if (r1g < nrows) {
                    float2 v = make_float2(acc[mt][nt][2] * dv1, acc[mt][nt][3] * dv1);
                    *(float2*)(outG + (size_t)r1g * BN + cc) = v;
                }
            }
        }
        buf ^= 1;
    }

    if (!PRESPLIT) GDC_WAIT();  // transitive ordering: fill done before we retire
}

// ---------------------------------------------------------------------------
// CSR aggregation + epilogue. OUTBF: emit bf16 hi/lo split pair (for next
// GEMM); else emit fp32. PDL: waits for predecessor (the GEMM) at the top.
// ---------------------------------------------------------------------------
template <int D, bool RELU, bool OUTBF>
__global__ void aggregate_kernel(const float* __restrict__ g,
                                 const int* __restrict__ rowptr,
                                 const int* __restrict__ csr,
                                 const float* __restrict__ dinv,
                                 const float* __restrict__ bias,
                                 float* __restrict__ out,
                                 uint2* __restrict__ outHi,
                                 uint2* __restrict__ outLo, int n) {
    GDC_WAIT();
    constexpr int TPN = D / 4;
    int t = blockIdx.x * blockDim.x + threadIdx.x;
    int v = t / TPN;
    int l = t % TPN;
    if (v >= n) return;
    const float4* g4 = (const float4*)g;

    float4 acc = g4[(size_t)v * TPN + l];   // self-loop
    int beg = rowptr[v], end = rowptr[v + 1];
    int j = beg;
    for (; j + 2 <= end; j += 2) {
        int s0 = csr[j], s1 = csr[j + 1];
        float4 m0 = g4[(size_t)s0 * TPN + l];
        float4 m1 = g4[(size_t)s1 * TPN + l];
        acc.x += m0.x + m1.x;
        acc.y += m0.y + m1.y;
        acc.z += m0.z + m1.z;
        acc.w += m0.w + m1.w;
    }
    if (j < end) {
        float4 m = g4[(size_t)csr[j] * TPN + l];
        acc.x += m.x; acc.y += m.y; acc.z += m.z; acc.w += m.w;
    }

    float dv = dinv[v];
    float4 b = ((const float4*)bias)[l];
    acc.x = acc.x * dv + b.x;
    acc.y = acc.y * dv + b.y;
    acc.z = acc.z * dv + b.z;
    acc.w = acc.w * dv + b.w;
    if (RELU) {
        acc.x = fmaxf(acc.x, 0.f);
        acc.y = fmaxf(acc.y, 0.f);
        acc.z = fmaxf(acc.z, 0.f);
        acc.w = fmaxf(acc.w, 0.f);
    }
    if (OUTBF) {
        __nv_bfloat16 h0, h1, h2, h3, l0, l1, l2, l3;
        split_bf(acc.x, h0, l0);
        split_bf(acc.y, h1, l1);
        split_bf(acc.z, h2, l2);
        split_bf(acc.w, h3, l3);
        uint2 hv = make_uint2(pack_bf2(h0, h1), pack_bf2(h2, h3));
        uint2 lv = make_uint2(pack_bf2(l0, l1), pack_bf2(l2, l3));
        outHi[(size_t)v * TPN + l] = hv;
        outLo[(size_t)v * TPN + l] = lv;
    } else {
        ((float4*)out)[(size_t)v * TPN + l] = acc;
    }
}

// ---------------------------------------------------------------------------
__global__ void decode_kernel(const float* __restrict__ z,
                              const int* __restrict__ ia,
                              const int* __restrict__ ib,
                              float* __restrict__ out, int npairs) {
    GDC_WAIT();
    int t = blockIdx.x * blockDim.x + threadIdx.x;
    int p = t >> 4;
    int l = t & 15;
    if (p >= npairs) return;
    int a = ia[p];
    int b = ib[p];
    float4 va = ((const float4*)z)[(size_t)a * 16 + l];
    float4 vb = ((const float4*)z)[(size_t)b * 16 + l];
    float s = va.x * vb.x + va.y * vb.y + va.z * vb.z + va.w * vb.w;
#pragma unroll
    for (int off = 8; off > 0; off >>= 1)
        s += __shfl_down_sync(0xffffffffu, s, off, 16);
    if (l == 0) out[p] = s;
}

// ---------------------------------------------------------------------------
// PDL launch helper: secondary kernel may start while the predecessor runs;
// device code orders itself via griddepcontrol.wait.
// ---------------------------------------------------------------------------
template <typename F, typename... Args>
static inline void pdl_launch(F kern, dim3 grid, dim3 block, size_t smem,
                              Args... args) {
    cudaLaunchConfig_t cfg = {};
    cfg.gridDim = grid;
    cfg.blockDim = block;
    cfg.dynamicSmemBytes = smem;
    cfg.stream = 0;
    cudaLaunchAttribute attr[1];
    attr[0].id = cudaLaunchAttributeProgrammaticStreamSerialization;
    attr[0].val.programmaticStreamSerializationAllowed = 1;
    cfg.attrs = attr;
    cfg.numAttrs = 1;
    cudaLaunchKernelEx(&cfg, kern, args...);
}

// ---------------------------------------------------------------------------
extern "C" void kernel_launch(void* const* d_in, const int* in_sizes, int n_in,
                              void* d_out, int out_size) {
    const float* x = (const float*)d_in[0];
    const int* ei = (const int*)d_in[1];        // int32
    const int* eli = (const int*)d_in[2];
    const float* W1 = (const float*)d_in[3];
    const float* b1 = (const float*)d_in[4];
    const float* W2 = (const float*)d_in[5];
    const float* b2 = (const float*)d_in[6];
    const float* W3 = (const float*)d_in[7];
    const float* b3 = (const float*)d_in[8];
    float* out = (float*)d_out;

    const int N = in_sizes[0] / 128;
    const int E = in_sizes[1] / 2;
    const int EL = in_sizes[2] / 2;

    const int* src = ei;
    const int* dst = ei + E;

    float* dinv;  cudaGetSymbolAddress((void**)&dinv, g_dinv);
    float* bufG;  cudaGetSymbolAddress((void**)&bufG, g_bufG);
    float* bufH;  cudaGetSymbolAddress((void**)&bufH, g_bufH);
    int* cnt;     cudaGetSymbolAddress((void**)&cnt, g_cnt);
    int* cur;     cudaGetSymbolAddress((void**)&cur, g_cur);
    int* rowptr;  cudaGetSymbolAddress((void**)&rowptr, g_rowptr);
    int* csr;     cudaGetSymbolAddress((void**)&csr, g_csr);
    uint4* hHi;   cudaGetSymbolAddress((void**)&hHi, g_hHi);
    uint4* hLo;   cudaGetSymbolAddress((void**)&hLo, g_hLo);
    __nv_bfloat16 *w1h, *w1l, *w2h, *w2l, *w3h, *w3l;
    cudaGetSymbolAddress((void**)&w1h, g_W1hi);
    cudaGetSymbolAddress((void**)&w1l, g_W1lo);
    cudaGetSymbolAddress((void**)&w2h, g_W2hi);
    cudaGetSymbolAddress((void**)&w2l, g_W2lo);
    cudaGetSymbolAddress((void**)&w3h, g_W3hi);
    cudaGetSymbolAddress((void**)&w3l, g_W3lo);

    constexpr int SROW = 272;
    constexpr int SMEM128 = 2 * 128 * SROW + 2 * (2 * 128 * SROW);  // 208896
    constexpr int SMEM64  = 2 * 64 * SROW + 2 * (2 * 128 * SROW);   // 174080
    cudaFuncSetAttribute(gemm_mma_kernel<128, false>,
                         cudaFuncAttributeMaxDynamicSharedMemorySize, SMEM128);
    cudaFuncSetAttribute(gemm_mma_kernel<128, true>,
                         cudaFuncAttributeMaxDynamicSharedMemorySize, SMEM128);
    cudaFuncSetAttribute(gemm_mma_kernel<64, true>,
                         cudaFuncAttributeMaxDynamicSharedMemorySize, SMEM64);

    const int TB = 256;
    const int ntiles = (N + 127) / 128;
    const int persGrid = 148;
    const int agg128 = (N * 32 + TB - 1) / TB;
    const int agg64  = (N * 16 + TB - 1) / TB;
    const int prepGrid = (max(N, 40960) + TB - 1) / TB;

    // prologue: prep -> count -> scan -> fill (PDL top-waits hide launch gaps)
    prep_kernel<<<prepGrid, TB>>>(cnt, cur, N, W1, W2, W3);
    pdl_launch(count_kernel, dim3((E + TB - 1) / TB), dim3(TB), (size_t)0,
               dst, cnt, E);
    pdl_launch(scan_dinv_kernel, dim3(1), dim3(1024), (size_t)0,
               (const int*)cnt, rowptr, dinv, N);
    pdl_launch(fill_kernel, dim3((E + TB - 1) / TB), dim3(TB), (size_t)0,
               src, dst, (const int*)rowptr, cur, csr, E);

    // layer-1 GEMM — PDL: overlaps fill (no data dependence; end-wait only)
    pdl_launch(gemm_mma_kernel<128, false>, dim3(persGrid), dim3(512), (size_t)SMEM128,
               x, (const uint4*)nullptr, (const uint4*)nullptr,
               (const __nv_bfloat16*)w1h, (const __nv_bfloat16*)w1l,
               (const float*)dinv, bufG, N, ntiles);

    // layer 1 aggregate -> bf16 hi/lo activation
    pdl_launch(aggregate_kernel<128, true, true>, dim3(agg128), dim3(TB), (size_t)0,
               (const float*)bufG, (const int*)rowptr, (const int*)csr,
               (const float*)dinv, b1, (float*)nullptr, (uint2*)hHi, (uint2*)hLo, N);

    // layer 2 (pre-split A)
    pdl_launch(gemm_mma_kernel<128, true>, dim3(persGrid), dim3(512), (size_t)SMEM128,
               (const float*)nullptr, (const uint4*)hHi, (const uint4*)hLo,
               (const __nv_bfloat16*)w2h, (const __nv_bfloat16*)w2l,
               (const float*)dinv, bufG, N, ntiles);
    pdl_launch(aggregate_kernel<128, true, true>, dim3(agg128), dim3(TB), (size_t)0,
               (const float*)bufG, (const int*)rowptr, (const int*)csr,
               (const float*)dinv, b2, (float*)nullptr, (uint2*)hHi, (uint2*)hLo, N);

    // layer 3 (D=64, pre-split A, fp32 out, no relu)
    pdl_launch(gemm_mma_kernel<64, true>, dim3(persGrid), dim3(512), (size_t)SMEM64,
               (const float*)nullptr, (const uint4*)hHi, (const uint4*)hLo,
               (const __nv_bfloat16*)w3h, (const __nv_bfloat16*)w3l,
               (const float*)dinv, bufG, N, ntiles);
    pdl_launch(aggregate_kernel<64, false, false>, dim3(agg64), dim3(TB), (size_t)0,
               (const float*)bufG, (const int*)rowptr, (const int*)csr,
               (const float*)dinv, b3, bufH, (uint2*)nullptr, (uint2*)nullptr, N);

    // decode
    pdl_launch(decode_kernel, dim3((int)(((long long)EL * 16 + TB - 1) / TB)),
               dim3(TB), (size_t)0,
               (const float*)bufH, (const int*)eli, (const int*)(eli + EL), out, EL);
}